// round 6
// baseline (speedup 1.0000x reference)
#include <cuda_runtime.h>
#include <cstdint>

// Problem constants (fixed by setup_inputs)
#define L1TOK   9360
#define DIMM    5120
#define KVD     1536
#define NHEADS  40
#define HDIM    128
#define LATOK   96
#define NFRAMES 6
#define HWTOK   1560

// Scratch (device globals: allocation-free)
// g_x, g_wq, g_wo, g_o hold tf32-rounded, K-PERMUTED data:
// within each group of 8 K-columns, order is {k0,k4,k1,k5,k2,k6,k3,k7}
__device__ float g_x [(size_t)L1TOK * DIMM];
__device__ float g_wq[(size_t)DIMM  * DIMM];
__device__ float g_wo[(size_t)DIMM  * DIMM];
__device__ float g_q [(size_t)L1TOK * DIMM];
__device__ float g_k [(size_t)LATOK * DIMM];
__device__ float g_v [(size_t)LATOK * DIMM];
__device__ float g_o [(size_t)L1TOK * DIMM];

// ---------------------------------------------------------------------------
// Helpers
// ---------------------------------------------------------------------------
__device__ __forceinline__ uint32_t f2tf32(float x) {
    uint32_t u;
    asm("cvt.rna.tf32.f32 %0, %1;" : "=r"(u) : "f"(x));
    return u;
}
__device__ __forceinline__ uint32_t smem_u32(const void* p) {
    uint32_t a;
    asm("{ .reg .u64 t; cvta.to.shared.u64 t, %1; cvt.u32.u64 %0, t; }" : "=r"(a) : "l"(p));
    return a;
}
__device__ __forceinline__ void mma_tf32(float* c, const uint32_t* a, uint32_t b0, uint32_t b1) {
    asm volatile(
        "mma.sync.aligned.m16n8k8.row.col.f32.tf32.tf32.f32 "
        "{%0,%1,%2,%3}, {%4,%5,%6,%7}, {%8,%9}, {%0,%1,%2,%3};\n"
        : "+f"(c[0]), "+f"(c[1]), "+f"(c[2]), "+f"(c[3])
        : "r"(a[0]), "r"(a[1]), "r"(a[2]), "r"(a[3]), "r"(b0), "r"(b1));
}
__device__ __forceinline__ void cp16(uint32_t dst, const float* src, bool pred) {
    asm volatile("cp.async.ca.shared.global [%0], [%1], 16, %2;"
                 :: "r"(dst), "l"(src), "r"(pred ? 16 : 0));
}
__device__ __forceinline__ void cp_commit() {
    asm volatile("cp.async.commit_group;" ::: "memory");
}
__device__ __forceinline__ void cp_wait2() {
    asm volatile("cp.async.wait_group 2;" ::: "memory");
}

// ---------------------------------------------------------------------------
// Big GEMM: C[M,5120] = A[M,5120] @ B[5120,5120]^T + bias
// A, B are tf32-rounded AND K-permuted (see above).
// CTA tile: 256(M) x 128(N), BK=16, 4-stage cp.async pipeline, 256 threads,
// 8 warps in 4(m) x 2(n), warp tile 64x64. ONE barrier per K-iteration.
// Stage rows padded to 24 floats (96 B) -> conflict-free LDS.64.
// ---------------------------------------------------------------------------
#define BKQ 16
#define SROWF 24
#define STG_A_F (256 * SROWF)         // 6144 floats (24576 B)
#define STG_B_F (128 * SROWF)         // 3072 floats (12288 B)
#define STG_F   (STG_A_F + STG_B_F)   // 9216 floats (36864 B)
#define NSTG 4
#define GSMEM (NSTG * STG_F * 4)      // 147456 B
#define KTQ (DIMM / BKQ)              // 320

__global__ void __launch_bounds__(256, 1)
gemm_tc_kernel(const float* __restrict__ A, const float* __restrict__ B,
               const float* __restrict__ bias, float* __restrict__ C, int M)
{
    extern __shared__ float smp[];
    const uint32_t sbase = smem_u32(smp);
    const int t    = threadIdx.x;
    const int warp = t >> 5;
    const int lane = t & 31;
    const int wm   = warp >> 1;      // 0..3  (64 rows)
    const int wn   = warp & 1;       // 0..1  (64 cols)
    const int g    = lane >> 2;
    const int tg   = lane & 3;
    const int n0   = blockIdx.x * 128;
    const int m0   = blockIdx.y * 256;

    float acc[4][8][4];
    #pragma unroll
    for (int i = 0; i < 4; i++)
        #pragma unroll
        for (int j = 0; j < 8; j++)
            #pragma unroll
            for (int r = 0; r < 4; r++) acc[i][j][r] = 0.f;

    // --- stage fill: 6 cp.async 16B per thread (A 4, B 2) ---
    auto fill = [&](int stage, int kt) {
        const int k0 = kt * BKQ;
        const uint32_t sb = sbase + stage * (STG_F * 4);
        #pragma unroll
        for (int i = 0; i < 4; i++) {           // A: 1024 chunks
            int id  = t + i * 256;
            int row = id >> 2, c4 = id & 3;
            cp16(sb + row * 96 + c4 * 16,
                 A + (size_t)(m0 + row) * DIMM + k0 + c4 * 4,
                 (m0 + row) < M);
        }
        #pragma unroll
        for (int i = 0; i < 2; i++) {           // B: 512 chunks
            int id  = t + i * 256;
            int row = id >> 2, c4 = id & 3;
            cp16(sb + STG_A_F * 4 + row * 96 + c4 * 16,
                 B + (size_t)(n0 + row) * DIMM + k0 + c4 * 4, true);
        }
    };

    // prologue: stages 0..2
    #pragma unroll
    for (int s = 0; s < 3; s++) { fill(s, s); cp_commit(); }

    const int aoff0 = (wm * 64 + g) * SROWF + 2 * tg;
    const int boff0 = STG_A_F + (wn * 64 + g) * SROWF + 2 * tg;

    for (int kt = 0; kt < KTQ; ++kt) {
        cp_wait2();
        __syncthreads();      // single barrier: stage kt visible; stage kt-1 reads done

        const int buf = kt & 3;
        if (kt + 3 < KTQ) fill((kt + 3) & 3, kt + 3);
        cp_commit();

        const float* st = smp + buf * STG_F;
        #pragma unroll
        for (int ks = 0; ks < 2; ++ks) {
            const int kk = ks * 8;
            uint32_t af[4][4];
            #pragma unroll
            for (int mt = 0; mt < 4; ++mt) {
                const int ao = aoff0 + mt * (16 * SROWF) + kk;
                float2 lo = *(const float2*)(st + ao);                 // rows g:   k tg, tg+4
                float2 hi = *(const float2*)(st + ao + 8 * SROWF);     // rows g+8: k tg, tg+4
                af[mt][0] = __float_as_uint(lo.x);
                af[mt][1] = __float_as_uint(hi.x);
                af[mt][2] = __float_as_uint(lo.y);
                af[mt][3] = __float_as_uint(hi.y);
            }
            #pragma unroll
            for (int nt = 0; nt < 8; ++nt) {
                const int bo = boff0 + nt * (8 * SROWF) + kk;
                float2 bb = *(const float2*)(st + bo);                 // col g: k tg, tg+4
                uint32_t b0 = __float_as_uint(bb.x);
                uint32_t b1 = __float_as_uint(bb.y);
                #pragma unroll
                for (int mt = 0; mt < 4; ++mt)
                    mma_tf32(acc[mt][nt], af[mt], b0, b1);
            }
        }
    }

    // --- epilogue ---
    #pragma unroll
    for (int mt = 0; mt < 4; ++mt) {
        const int r0 = m0 + wm * 64 + mt * 16 + g;
        #pragma unroll
        for (int nt = 0; nt < 8; ++nt) {
            const int c0 = n0 + wn * 64 + nt * 8 + tg * 2;
            const float b0v = bias[c0];
            const float b1v = bias[c0 + 1];
            if (r0 < M) {
                float2 o0 = { acc[mt][nt][0] + b0v, acc[mt][nt][1] + b1v };
                *(float2*)(C + (size_t)r0 * DIMM + c0) = o0;
            }
            if (r0 + 8 < M) {
                float2 o1 = { acc[mt][nt][2] + b0v, acc[mt][nt][3] + b1v };
                *(float2*)(C + (size_t)(r0 + 8) * DIMM + c0) = o1;
            }
        }
    }
}

// ---------------------------------------------------------------------------
// Pre-round + K-permute kernel:
// per 8-float group: out = {k0,k4,k1,k5,k2,k6,k3,k7}, all tf32-rounded.
// ---------------------------------------------------------------------------
__global__ void __launch_bounds__(256)
round_perm_kernel(float* __restrict__ dst, const float* __restrict__ src, int n8)
{
    const int stride = gridDim.x * 256;
    for (int i = blockIdx.x * 256 + threadIdx.x; i < n8; i += stride) {
        float4 a = ((const float4*)src)[2 * i];
        float4 b = ((const float4*)src)[2 * i + 1];
        uint4 o0 = { f2tf32(a.x), f2tf32(b.x), f2tf32(a.y), f2tf32(b.y) };
        uint4 o1 = { f2tf32(a.z), f2tf32(b.z), f2tf32(a.w), f2tf32(b.w) };
        ((uint4*)dst)[2 * i]     = o0;
        ((uint4*)dst)[2 * i + 1] = o1;
    }
}

// ---------------------------------------------------------------------------
// Legacy TF32 GEMM for small K/V projections (M=96): C = A @ B^T + bias
// ---------------------------------------------------------------------------
__device__ __forceinline__ void mma_tf32b(float* c, const uint32_t* a, const uint32_t* b) {
    asm volatile(
        "mma.sync.aligned.m16n8k8.row.col.f32.tf32.tf32.f32 "
        "{%0,%1,%2,%3}, {%4,%5,%6,%7}, {%8,%9}, {%0,%1,%2,%3};\n"
        : "+f"(c[0]), "+f"(c[1]), "+f"(c[2]), "+f"(c[3])
        : "r"(a[0]), "r"(a[1]), "r"(a[2]), "r"(a[3]), "r"(b[0]), "r"(b[1]));
}
#define BM 128
#define BN 128
#define SROW 36

__global__ void __launch_bounds__(256, 1)
gemm_tf32_kernel(const float* __restrict__ A, const float* __restrict__ B,
                 const float* __restrict__ bias, float* __restrict__ C,
                 int M, int N, int K)
{
    extern __shared__ float fsm[];
    float* sA = fsm;
    float* sB = fsm + 2 * BM * SROW;
    const int t = threadIdx.x, warp = t >> 5, lane = t & 31;
    const int wm = warp >> 2, wn = warp & 3, g = lane >> 2, tg = lane & 3;
    const int row0 = blockIdx.y * BM, col0 = blockIdx.x * BN;

    float acc[4][4][4];
    #pragma unroll
    for (int i = 0; i < 4; i++) for (int j = 0; j < 4; j++) for (int r = 0; r < 4; r++) acc[i][j][r] = 0.f;
    float4 rA[4], rB[4];
    const int KTl = K / 32;

    auto LDG = [&](int kt) {
        const int k0 = kt * 32;
        #pragma unroll
        for (int i = 0; i < 4; i++) {
            int id = t + i * 256, r = id >> 3, c4 = id & 7;
            int ga = row0 + r;
            rA[i] = (ga < M) ? *(const float4*)(A + (size_t)ga * K + k0 + c4 * 4) : make_float4(0.f,0.f,0.f,0.f);
            rB[i] = *(const float4*)(B + (size_t)(col0 + r) * K + k0 + c4 * 4);
        }
    };
    auto STS = [&](int buf) {
        float* dA = sA + buf * BM * SROW;
        float* dB = sB + buf * BN * SROW;
        #pragma unroll
        for (int i = 0; i < 4; i++) {
            int id = t + i * 256, r = id >> 3, c4 = id & 7;
            uint4 ua = { f2tf32(rA[i].x), f2tf32(rA[i].y), f2tf32(rA[i].z), f2tf32(rA[i].w) };
            *(uint4*)(dA + r * SROW + c4 * 4) = ua;
            uint4 ub = { f2tf32(rB[i].x), f2tf32(rB[i].y), f2tf32(rB[i].z), f2tf32(rB[i].w) };
            *(uint4*)(dB + r * SROW + c4 * 4) = ub;
        }
    };

    LDG(0); STS(0); __syncthreads();
    int buf = 0;
    for (int kt = 0; kt < KTl; ++kt) {
        if (kt + 1 < KTl) LDG(kt + 1);
        const uint32_t* uA = (const uint32_t*)(sA + buf * BM * SROW);
        const uint32_t* uB = (const uint32_t*)(sB + buf * BN * SROW);
        #pragma unroll
        for (int ks = 0; ks < 4; ++ks) {
            const int kk = ks * 8;
            uint32_t af[4][4], bf[4][2];
            #pragma unroll
            for (int mt = 0; mt < 4; ++mt) {
                int r = wm * 64 + mt * 16 + g;
                af[mt][0] = uA[r * SROW + kk + tg];
                af[mt][1] = uA[(r + 8) * SROW + kk + tg];
                af[mt][2] = uA[r * SROW + kk + tg + 4];
                af[mt][3] = uA[(r + 8) * SROW + kk + tg + 4];
            }
            #pragma unroll
            for (int nt = 0; nt < 4; ++nt) {
                int n = wn * 32 + nt * 8 + g;
                bf[nt][0] = uB[n * SROW + kk + tg];
                bf[nt][1] = uB[n * SROW + kk + tg + 4];
            }
            #pragma unroll
            for (int mt = 0; mt < 4; ++mt)
                #pragma unroll
                for (int nt = 0; nt < 4; ++nt)
                    mma_tf32b(acc[mt][nt], af[mt], bf[nt]);
        }
        if (kt + 1 < KTl) STS(buf ^ 1);
        __syncthreads();
        buf ^= 1;
    }
    #pragma unroll
    for (int mt = 0; mt < 4; ++mt) {
        int r0 = row0 + wm * 64 + mt * 16 + g;
        #pragma unroll
        for (int nt = 0; nt < 4; ++nt) {
            int c0 = col0 + wn * 32 + nt * 8 + tg * 2;
            float b0v = bias[c0], b1v = bias[c0 + 1];
            if (r0 < M) {
                C[(size_t)r0 * N + c0]     = acc[mt][nt][0] + b0v;
                C[(size_t)r0 * N + c0 + 1] = acc[mt][nt][1] + b1v;
            }
            if (r0 + 8 < M) {
                C[(size_t)(r0 + 8) * N + c0]     = acc[mt][nt][2] + b0v;
                C[(size_t)(r0 + 8) * N + c0 + 1] = acc[mt][nt][3] + b1v;
            }
        }
    }
}

// ---------------------------------------------------------------------------
// RMSNorm (rows of 5120)
// ---------------------------------------------------------------------------
__global__ void __launch_bounds__(256)
rmsnorm_kernel(float* __restrict__ buf, const float* __restrict__ gvec)
{
    const int row = blockIdx.x, t = threadIdx.x, lane = t & 31, warp = t >> 5;
    float4* p4 = (float4*)(buf + (size_t)row * DIMM);
    const float4* g4 = (const float4*)gvec;
    float4 v[5]; float ss = 0.f;
    #pragma unroll
    for (int i = 0; i < 5; i++) {
        v[i] = p4[t + i * 256];
        ss += v[i].x*v[i].x + v[i].y*v[i].y + v[i].z*v[i].z + v[i].w*v[i].w;
    }
    #pragma unroll
    for (int off = 16; off > 0; off >>= 1) ss += __shfl_xor_sync(0xffffffffu, ss, off);
    __shared__ float red[8]; __shared__ float stot;
    if (lane == 0) red[warp] = ss;
    __syncthreads();
    if (t < 8) {
        float tot = red[t];
        #pragma unroll
        for (int off = 4; off > 0; off >>= 1) tot += __shfl_xor_sync(0xffu, tot, off);
        if (t == 0) stot = tot;
    }
    __syncthreads();
    const float inv = rsqrtf(stot / (float)DIMM + 1e-6f);
    #pragma unroll
    for (int i = 0; i < 5; i++) {
        float4 gv = g4[t + i * 256];
        float4 o = { v[i].x*inv*gv.x, v[i].y*inv*gv.y, v[i].z*inv*gv.z, v[i].w*inv*gv.w };
        p4[t + i * 256] = o;
    }
}

// ---------------------------------------------------------------------------
// Attention: per (frame, head), 16 keys.
// Output written tf32-rounded AND K-permuted (feeds O-projection as A).
// ---------------------------------------------------------------------------
#define SKPAD 132
__global__ void __launch_bounds__(128)
attn_kernel(const float* __restrict__ q, const float* __restrict__ k,
            const float* __restrict__ v, float* __restrict__ o)
{
    const int fh = blockIdx.x, f = fh / NHEADS, h = fh % NHEADS;
    __shared__ float sk[16][SKPAD];
    __shared__ float sv[16][SKPAD];
    const int t = threadIdx.x;
    #pragma unroll
    for (int i = 0; i < 4; i++) {
        int id = t + i * 128, j = id >> 5, c4 = id & 31;
        size_t goff = ((size_t)(f * 16 + j)) * DIMM + h * HDIM + c4 * 4;
        *(float4*)(&sk[j][c4 * 4]) = *(const float4*)(k + goff);
        *(float4*)(&sv[j][c4 * 4]) = *(const float4*)(v + goff);
    }
    __syncthreads();
    const int warp = t >> 5, lane = t & 31;
    const float scale = 0.08838834764831844f;
    #pragma unroll
    for (int rr = 0; rr < 4; ++rr) {
        const int pos = blockIdx.y * 16 + warp * 4 + rr;
        if (pos >= HWTOK) break;
        const float4* q4 = (const float4*)(q + ((size_t)(f * HWTOK + pos)) * DIMM + h * HDIM);
        float logit = -1e30f;
        if (lane < 16) {
            float s = 0.f;
            #pragma unroll
            for (int c = 0; c < 32; c++) {
                float4 a = q4[c];
                float4 b = *(const float4*)(&sk[lane][c * 4]);
                s += a.x*b.x + a.y*b.y + a.z*b.z + a.w*b.w;
            }
            logit = s * scale;
        }
        float m = logit;
        #pragma unroll
        for (int off = 8; off > 0; off >>= 1) m = fmaxf(m, __shfl_xor_sync(0xffffffffu, m, off, 16));
        float e = (lane < 16) ? expf(logit - m) : 0.f;
        float ssum = e;
        #pragma unroll
        for (int off = 8; off > 0; off >>= 1) ssum += __shfl_xor_sync(0xffffffffu, ssum, off, 16);
        float att = (lane < 16) ? (e / ssum) : 0.f;
        float4 oacc = make_float4(0.f, 0.f, 0.f, 0.f);
        #pragma unroll
        for (int j = 0; j < 16; j++) {
            float aj = __shfl_sync(0xffffffffu, att, j);
            float4 vv = *(const float4*)(&sv[j][lane * 4]);
            oacc.x += aj*vv.x; oacc.y += aj*vv.y; oacc.z += aj*vv.z; oacc.w += aj*vv.w;
        }
        // Store tf32-rounded, K-permuted: old col 4L+j -> group (L>>1)*8, slot 2*j + (L&1)
        float* orow = o + ((size_t)(f * HWTOK + pos)) * DIMM + h * HDIM + (lane >> 1) * 8 + (lane & 1);
        orow[0] = __uint_as_float(f2tf32(oacc.x));
        orow[2] = __uint_as_float(f2tf32(oacc.y));
        orow[4] = __uint_as_float(f2tf32(oacc.z));
        orow[6] = __uint_as_float(f2tf32(oacc.w));
    }
}

// ---------------------------------------------------------------------------
// Launcher
// ---------------------------------------------------------------------------
extern "C" void kernel_launch(void* const* d_in, const int* in_sizes, int n_in,
                              void* d_out, int out_size)
{
    const float* x   = (const float*)d_in[0];
    const float* ctx = (const float*)d_in[1];
    const float* Wq  = (const float*)d_in[6];
    const float* bq  = (const float*)d_in[7];
    const float* Wk  = (const float*)d_in[8];
    const float* bk  = (const float*)d_in[9];
    const float* Wv  = (const float*)d_in[10];
    const float* bv  = (const float*)d_in[11];
    const float* Wo  = (const float*)d_in[12];
    const float* bo  = (const float*)d_in[13];
    const float* gq  = (const float*)d_in[14];
    const float* gk  = (const float*)d_in[15];
    float* out = (float*)d_out;

    float *xb, *wqb, *wob, *qb, *kb, *vb, *ob;
    cudaGetSymbolAddress((void**)&xb,  g_x);
    cudaGetSymbolAddress((void**)&wqb, g_wq);
    cudaGetSymbolAddress((void**)&wob, g_wo);
    cudaGetSymbolAddress((void**)&qb,  g_q);
    cudaGetSymbolAddress((void**)&kb,  g_k);
    cudaGetSymbolAddress((void**)&vb,  g_v);
    cudaGetSymbolAddress((void**)&ob,  g_o);

    cudaFuncSetAttribute(gemm_tc_kernel, cudaFuncAttributeMaxDynamicSharedMemorySize, GSMEM);
    const int lsmem = 2 * (BM * SROW + BN * SROW) * (int)sizeof(float);
    cudaFuncSetAttribute(gemm_tf32_kernel, cudaFuncAttributeMaxDynamicSharedMemorySize, lsmem);

    // Pre-round + K-permute inputs feeding the big GEMMs
    round_perm_kernel<<<2048, 256>>>(xb,  x,  (int)((size_t)L1TOK * DIMM / 8));
    round_perm_kernel<<<2048, 256>>>(wqb, Wq, (int)((size_t)DIMM  * DIMM / 8));
    round_perm_kernel<<<2048, 256>>>(wob, Wo, (int)((size_t)DIMM  * DIMM / 8));

    // Q projection: g_q = x @ Wq^T + bq
    {
        dim3 grid(DIMM / 128, (L1TOK + 255) / 256);
        gemm_tc_kernel<<<grid, 256, GSMEM>>>(xb, wqb, bq, qb, L1TOK);
    }
    // K / V projections (tiny)
    {
        dim3 grid(DIMM / BN, 1);
        gemm_tf32_kernel<<<grid, 256, lsmem>>>(ctx, Wk, bk, kb, LATOK, DIMM, KVD);
        gemm_tf32_kernel<<<grid, 256, lsmem>>>(ctx, Wv, bv, vb, LATOK, DIMM, KVD);
    }
    // RMSNorm
    rmsnorm_kernel<<<L1TOK, 256>>>(qb, gq);
    rmsnorm_kernel<<<LATOK, 256>>>(kb, gk);
    // Attention (writes tf32-rounded, K-permuted o)
    {
        dim3 grid(NFRAMES * NHEADS, (HWTOK + 15) / 16);
        attn_kernel<<<grid, 128>>>(qb, kb, vb, ob);
    }
    // Output projection: out = o @ Wo^T + bo
    {
        dim3 grid(DIMM / 128, (L1TOK + 255) / 256);
        gemm_tc_kernel<<<grid, 256, GSMEM>>>(ob, wob, bo, out, L1TOK);
    }
}

// round 7
// speedup vs baseline: 1.0693x; 1.0693x over previous
#include <cuda_runtime.h>
#include <cstdint>

// Problem constants (fixed by setup_inputs)
#define L1TOK   9360
#define DIMM    5120
#define KVD     1536
#define NHEADS  40
#define HDIM    128
#define LATOK   96
#define NFRAMES 6
#define HWTOK   1560

// Scratch (device globals: allocation-free)
// g_x, g_wq, g_wo, g_o hold tf32-rounded, K-PERMUTED data:
// within each group of 8 K-columns, order is {k0,k4,k1,k5,k2,k6,k3,k7}
__device__ float g_x [(size_t)L1TOK * DIMM];
__device__ float g_wq[(size_t)DIMM  * DIMM];
__device__ float g_wo[(size_t)DIMM  * DIMM];
__device__ float g_q [(size_t)L1TOK * DIMM];
__device__ float g_k [(size_t)LATOK * DIMM];
__device__ float g_v [(size_t)LATOK * DIMM];
__device__ float g_o [(size_t)L1TOK * DIMM];

// ---------------------------------------------------------------------------
// Helpers
// ---------------------------------------------------------------------------
__device__ __forceinline__ uint32_t f2tf32(float x) {
    uint32_t u;
    asm("cvt.rna.tf32.f32 %0, %1;" : "=r"(u) : "f"(x));
    return u;
}
__device__ __forceinline__ uint32_t smem_u32(const void* p) {
    uint32_t a;
    asm("{ .reg .u64 t; cvta.to.shared.u64 t, %1; cvt.u32.u64 %0, t; }" : "=r"(a) : "l"(p));
    return a;
}
__device__ __forceinline__ void mma_tf32(float* c, const uint32_t* a, uint32_t b0, uint32_t b1) {
    asm volatile(
        "mma.sync.aligned.m16n8k8.row.col.f32.tf32.tf32.f32 "
        "{%0,%1,%2,%3}, {%4,%5,%6,%7}, {%8,%9}, {%0,%1,%2,%3};\n"
        : "+f"(c[0]), "+f"(c[1]), "+f"(c[2]), "+f"(c[3])
        : "r"(a[0]), "r"(a[1]), "r"(a[2]), "r"(a[3]), "r"(b0), "r"(b1));
}
__device__ __forceinline__ void cp16(uint32_t dst, const float* src, bool pred) {
    asm volatile("cp.async.ca.shared.global [%0], [%1], 16, %2;"
                 :: "r"(dst), "l"(src), "r"(pred ? 16 : 0));
}
__device__ __forceinline__ void cp_commit() {
    asm volatile("cp.async.commit_group;" ::: "memory");
}
__device__ __forceinline__ void cp_wait2() {
    asm volatile("cp.async.wait_group 2;" ::: "memory");
}

// ---------------------------------------------------------------------------
// Big GEMM: C[M,5120] = A[M,5120] @ B[5120,5120]^T + bias
// A, B are tf32-rounded AND K-permuted (see above).
// CTA tile: 256(M) x 128(N), BK=16, 4-stage cp.async pipeline, 512 threads,
// 16 warps in 4(m) x 4(n), warp tile 64x32 -> 64 acc regs/thread.
// ONE barrier per K-iteration. Stage rows padded to 24 floats (96 B).
// ---------------------------------------------------------------------------
#define BKQ 16
#define SROWF 24
#define STG_A_F (256 * SROWF)         // 6144 floats (24576 B)
#define STG_B_F (128 * SROWF)         // 3072 floats (12288 B)
#define STG_F   (STG_A_F + STG_B_F)   // 9216 floats (36864 B)
#define NSTG 4
#define GSMEM (NSTG * STG_F * 4)      // 147456 B
#define KTQ (DIMM / BKQ)              // 320

__global__ void __launch_bounds__(512, 1)
gemm_tc_kernel(const float* __restrict__ A, const float* __restrict__ B,
               const float* __restrict__ bias, float* __restrict__ C, int M)
{
    extern __shared__ float smp[];
    const uint32_t sbase = smem_u32(smp);
    const int t    = threadIdx.x;
    const int warp = t >> 5;
    const int lane = t & 31;
    const int wm   = warp >> 2;      // 0..3  (64 rows)
    const int wn   = warp & 3;       // 0..3  (32 cols)
    const int g    = lane >> 2;
    const int tg   = lane & 3;
    const int n0   = blockIdx.x * 128;
    const int m0   = blockIdx.y * 256;

    float acc[4][4][4];
    #pragma unroll
    for (int i = 0; i < 4; i++)
        #pragma unroll
        for (int j = 0; j < 4; j++)
            #pragma unroll
            for (int r = 0; r < 4; r++) acc[i][j][r] = 0.f;

    // --- stage fill: 3 cp.async 16B per thread (A 2, B 1) ---
    auto fill = [&](int stage, int kt) {
        const int k0 = kt * BKQ;
        const uint32_t sb = sbase + stage * (STG_F * 4);
        #pragma unroll
        for (int i = 0; i < 2; i++) {           // A: 1024 chunks
            int id  = t + i * 512;
            int row = id >> 2, c4 = id & 3;
            cp16(sb + row * 96 + c4 * 16,
                 A + (size_t)(m0 + row) * DIMM + k0 + c4 * 4,
                 (m0 + row) < M);
        }
        {                                        // B: 512 chunks
            int row = t >> 2, c4 = t & 3;
            cp16(sb + STG_A_F * 4 + row * 96 + c4 * 16,
                 B + (size_t)(n0 + row) * DIMM + k0 + c4 * 4, true);
        }
    };

    // prologue: stages 0..2
    #pragma unroll
    for (int s = 0; s < 3; s++) { fill(s, s); cp_commit(); }

    const int aoff0 = (wm * 64 + g) * SROWF + 2 * tg;
    const int boff0 = STG_A_F + (wn * 32 + g) * SROWF + 2 * tg;

    for (int kt = 0; kt < KTQ; ++kt) {
        cp_wait2();
        __syncthreads();      // stage kt visible; stage kt-1 reads complete

        const int buf = kt & 3;
        if (kt + 3 < KTQ) fill((kt + 3) & 3, kt + 3);
        cp_commit();

        const float* st = smp + buf * STG_F;
        #pragma unroll
        for (int ks = 0; ks < 2; ++ks) {
            const int kk = ks * 8;
            uint32_t af[4][4];
            #pragma unroll
            for (int mt = 0; mt < 4; ++mt) {
                const int ao = aoff0 + mt * (16 * SROWF) + kk;
                float2 lo = *(const float2*)(st + ao);                 // rows g:   k tg, tg+4
                float2 hi = *(const float2*)(st + ao + 8 * SROWF);     // rows g+8: k tg, tg+4
                af[mt][0] = __float_as_uint(lo.x);
                af[mt][1] = __float_as_uint(hi.x);
                af[mt][2] = __float_as_uint(lo.y);
                af[mt][3] = __float_as_uint(hi.y);
            }
            #pragma unroll
            for (int nt = 0; nt < 4; ++nt) {
                const int bo = boff0 + nt * (8 * SROWF) + kk;
                float2 bb = *(const float2*)(st + bo);                 // col g: k tg, tg+4
                uint32_t b0 = __float_as_uint(bb.x);
                uint32_t b1 = __float_as_uint(bb.y);
                #pragma unroll
                for (int mt = 0; mt < 4; ++mt)
                    mma_tf32(acc[mt][nt], af[mt], b0, b1);
            }
        }
    }

    // --- epilogue ---
    #pragma unroll
    for (int mt = 0; mt < 4; ++mt) {
        const int r0 = m0 + wm * 64 + mt * 16 + g;
        #pragma unroll
        for (int nt = 0; nt < 4; ++nt) {
            const int c0 = n0 + wn * 32 + nt * 8 + tg * 2;
            const float b0v = bias[c0];
            const float b1v = bias[c0 + 1];
            if (r0 < M) {
                float2 o0 = { acc[mt][nt][0] + b0v, acc[mt][nt][1] + b1v };
                *(float2*)(C + (size_t)r0 * DIMM + c0) = o0;
            }
            if (r0 + 8 < M) {
                float2 o1 = { acc[mt][nt][2] + b0v, acc[mt][nt][3] + b1v };
                *(float2*)(C + (size_t)(r0 + 8) * DIMM + c0) = o1;
            }
        }
    }
}

// ---------------------------------------------------------------------------
// Pre-round + K-permute kernel:
// per 8-float group: out = {k0,k4,k1,k5,k2,k6,k3,k7}, all tf32-rounded.
// ---------------------------------------------------------------------------
__global__ void __launch_bounds__(256)
round_perm_kernel(float* __restrict__ dst, const float* __restrict__ src, int n8)
{
    const int stride = gridDim.x * 256;
    for (int i = blockIdx.x * 256 + threadIdx.x; i < n8; i += stride) {
        float4 a = ((const float4*)src)[2 * i];
        float4 b = ((const float4*)src)[2 * i + 1];
        uint4 o0 = { f2tf32(a.x), f2tf32(b.x), f2tf32(a.y), f2tf32(b.y) };
        uint4 o1 = { f2tf32(a.z), f2tf32(b.z), f2tf32(a.w), f2tf32(b.w) };
        ((uint4*)dst)[2 * i]     = o0;
        ((uint4*)dst)[2 * i + 1] = o1;
    }
}

// ---------------------------------------------------------------------------
// Legacy TF32 GEMM for small K/V projections (M=96): C = A @ B^T + bias
// ---------------------------------------------------------------------------
__device__ __forceinline__ void mma_tf32b(float* c, const uint32_t* a, const uint32_t* b) {
    asm volatile(
        "mma.sync.aligned.m16n8k8.row.col.f32.tf32.tf32.f32 "
        "{%0,%1,%2,%3}, {%4,%5,%6,%7}, {%8,%9}, {%0,%1,%2,%3};\n"
        : "+f"(c[0]), "+f"(c[1]), "+f"(c[2]), "+f"(c[3])
        : "r"(a[0]), "r"(a[1]), "r"(a[2]), "r"(a[3]), "r"(b[0]), "r"(b[1]));
}
#define BM 128
#define BN 128
#define SROW 36

__global__ void __launch_bounds__(256, 1)
gemm_tf32_kernel(const float* __restrict__ A, const float* __restrict__ B,
                 const float* __restrict__ bias, float* __restrict__ C,
                 int M, int N, int K)
{
    extern __shared__ float fsm[];
    float* sA = fsm;
    float* sB = fsm + 2 * BM * SROW;
    const int t = threadIdx.x, warp = t >> 5, lane = t & 31;
    const int wm = warp >> 2, wn = warp & 3, g = lane >> 2, tg = lane & 3;
    const int row0 = blockIdx.y * BM, col0 = blockIdx.x * BN;

    float acc[4][4][4];
    #pragma unroll
    for (int i = 0; i < 4; i++) for (int j = 0; j < 4; j++) for (int r = 0; r < 4; r++) acc[i][j][r] = 0.f;
    float4 rA[4], rB[4];
    const int KTl = K / 32;

    auto LDG = [&](int kt) {
        const int k0 = kt * 32;
        #pragma unroll
        for (int i = 0; i < 4; i++) {
            int id = t + i * 256, r = id >> 3, c4 = id & 7;
            int ga = row0 + r;
            rA[i] = (ga < M) ? *(const float4*)(A + (size_t)ga * K + k0 + c4 * 4) : make_float4(0.f,0.f,0.f,0.f);
            rB[i] = *(const float4*)(B + (size_t)(col0 + r) * K + k0 + c4 * 4);
        }
    };
    auto STS = [&](int buf) {
        float* dA = sA + buf * BM * SROW;
        float* dB = sB + buf * BN * SROW;
        #pragma unroll
        for (int i = 0; i < 4; i++) {
            int id = t + i * 256, r = id >> 3, c4 = id & 7;
            uint4 ua = { f2tf32(rA[i].x), f2tf32(rA[i].y), f2tf32(rA[i].z), f2tf32(rA[i].w) };
            *(uint4*)(dA + r * SROW + c4 * 4) = ua;
            uint4 ub = { f2tf32(rB[i].x), f2tf32(rB[i].y), f2tf32(rB[i].z), f2tf32(rB[i].w) };
            *(uint4*)(dB + r * SROW + c4 * 4) = ub;
        }
    };

    LDG(0); STS(0); __syncthreads();
    int buf = 0;
    for (int kt = 0; kt < KTl; ++kt) {
        if (kt + 1 < KTl) LDG(kt + 1);
        const uint32_t* uA = (const uint32_t*)(sA + buf * BM * SROW);
        const uint32_t* uB = (const uint32_t*)(sB + buf * BN * SROW);
        #pragma unroll
        for (int ks = 0; ks < 4; ++ks) {
            const int kk = ks * 8;
            uint32_t af[4][4], bf[4][2];
            #pragma unroll
            for (int mt = 0; mt < 4; ++mt) {
                int r = wm * 64 + mt * 16 + g;
                af[mt][0] = uA[r * SROW + kk + tg];
                af[mt][1] = uA[(r + 8) * SROW + kk + tg];
                af[mt][2] = uA[r * SROW + kk + tg + 4];
                af[mt][3] = uA[(r + 8) * SROW + kk + tg + 4];
            }
            #pragma unroll
            for (int nt = 0; nt < 4; ++nt) {
                int n = wn * 32 + nt * 8 + g;
                bf[nt][0] = uB[n * SROW + kk + tg];
                bf[nt][1] = uB[n * SROW + kk + tg + 4];
            }
            #pragma unroll
            for (int mt = 0; mt < 4; ++mt)
                #pragma unroll
                for (int nt = 0; nt < 4; ++nt)
                    mma_tf32b(acc[mt][nt], af[mt], bf[nt]);
        }
        if (kt + 1 < KTl) STS(buf ^ 1);
        __syncthreads();
        buf ^= 1;
    }
    #pragma unroll
    for (int mt = 0; mt < 4; ++mt) {
        int r0 = row0 + wm * 64 + mt * 16 + g;
        #pragma unroll
        for (int nt = 0; nt < 4; ++nt) {
            int c0 = col0 + wn * 32 + nt * 8 + tg * 2;
            float b0v = bias[c0], b1v = bias[c0 + 1];
            if (r0 < M) {
                C[(size_t)r0 * N + c0]     = acc[mt][nt][0] + b0v;
                C[(size_t)r0 * N + c0 + 1] = acc[mt][nt][1] + b1v;
            }
            if (r0 + 8 < M) {
                C[(size_t)(r0 + 8) * N + c0]     = acc[mt][nt][2] + b0v;
                C[(size_t)(r0 + 8) * N + c0 + 1] = acc[mt][nt][3] + b1v;
            }
        }
    }
}

// ---------------------------------------------------------------------------
// RMSNorm (rows of 5120)
// ---------------------------------------------------------------------------
__global__ void __launch_bounds__(256)
rmsnorm_kernel(float* __restrict__ buf, const float* __restrict__ gvec)
{
    const int row = blockIdx.x, t = threadIdx.x, lane = t & 31, warp = t >> 5;
    float4* p4 = (float4*)(buf + (size_t)row * DIMM);
    const float4* g4 = (const float4*)gvec;
    float4 v[5]; float ss = 0.f;
    #pragma unroll
    for (int i = 0; i < 5; i++) {
        v[i] = p4[t + i * 256];
        ss += v[i].x*v[i].x + v[i].y*v[i].y + v[i].z*v[i].z + v[i].w*v[i].w;
    }
    #pragma unroll
    for (int off = 16; off > 0; off >>= 1) ss += __shfl_xor_sync(0xffffffffu, ss, off);
    __shared__ float red[8]; __shared__ float stot;
    if (lane == 0) red[warp] = ss;
    __syncthreads();
    if (t < 8) {
        float tot = red[t];
        #pragma unroll
        for (int off = 4; off > 0; off >>= 1) tot += __shfl_xor_sync(0xffu, tot, off);
        if (t == 0) stot = tot;
    }
    __syncthreads();
    const float inv = rsqrtf(stot / (float)DIMM + 1e-6f);
    #pragma unroll
    for (int i = 0; i < 5; i++) {
        float4 gv = g4[t + i * 256];
        float4 o = { v[i].x*inv*gv.x, v[i].y*inv*gv.y, v[i].z*inv*gv.z, v[i].w*inv*gv.w };
        p4[t + i * 256] = o;
    }
}

// ---------------------------------------------------------------------------
// Attention: per (frame, head), 16 keys.
// Output written tf32-rounded AND K-permuted (feeds O-projection as A).
// ---------------------------------------------------------------------------
#define SKPAD 132
__global__ void __launch_bounds__(128)
attn_kernel(const float* __restrict__ q, const float* __restrict__ k,
            const float* __restrict__ v, float* __restrict__ o)
{
    const int fh = blockIdx.x, f = fh / NHEADS, h = fh % NHEADS;
    __shared__ float sk[16][SKPAD];
    __shared__ float sv[16][SKPAD];
    const int t = threadIdx.x;
    #pragma unroll
    for (int i = 0; i < 4; i++) {
        int id = t + i * 128, j = id >> 5, c4 = id & 31;
        size_t goff = ((size_t)(f * 16 + j)) * DIMM + h * HDIM + c4 * 4;
        *(float4*)(&sk[j][c4 * 4]) = *(const float4*)(k + goff);
        *(float4*)(&sv[j][c4 * 4]) = *(const float4*)(v + goff);
    }
    __syncthreads();
    const int warp = t >> 5, lane = t & 31;
    const float scale = 0.08838834764831844f;
    #pragma unroll
    for (int rr = 0; rr < 4; ++rr) {
        const int pos = blockIdx.y * 16 + warp * 4 + rr;
        if (pos >= HWTOK) break;
        const float4* q4 = (const float4*)(q + ((size_t)(f * HWTOK + pos)) * DIMM + h * HDIM);
        float logit = -1e30f;
        if (lane < 16) {
            float s = 0.f;
            #pragma unroll
            for (int c = 0; c < 32; c++) {
                float4 a = q4[c];
                float4 b = *(const float4*)(&sk[lane][c * 4]);
                s += a.x*b.x + a.y*b.y + a.z*b.z + a.w*b.w;
            }
            logit = s * scale;
        }
        float m = logit;
        #pragma unroll
        for (int off = 8; off > 0; off >>= 1) m = fmaxf(m, __shfl_xor_sync(0xffffffffu, m, off, 16));
        float e = (lane < 16) ? expf(logit - m) : 0.f;
        float ssum = e;
        #pragma unroll
        for (int off = 8; off > 0; off >>= 1) ssum += __shfl_xor_sync(0xffffffffu, ssum, off, 16);
        float att = (lane < 16) ? (e / ssum) : 0.f;
        float4 oacc = make_float4(0.f, 0.f, 0.f, 0.f);
        #pragma unroll
        for (int j = 0; j < 16; j++) {
            float aj = __shfl_sync(0xffffffffu, att, j);
            float4 vv = *(const float4*)(&sv[j][lane * 4]);
            oacc.x += aj*vv.x; oacc.y += aj*vv.y; oacc.z += aj*vv.z; oacc.w += aj*vv.w;
        }
        // Store tf32-rounded, K-permuted: old col 4L+j -> group (L>>1)*8, slot 2*j + (L&1)
        float* orow = o + ((size_t)(f * HWTOK + pos)) * DIMM + h * HDIM + (lane >> 1) * 8 + (lane & 1);
        orow[0] = __uint_as_float(f2tf32(oacc.x));
        orow[2] = __uint_as_float(f2tf32(oacc.y));
        orow[4] = __uint_as_float(f2tf32(oacc.z));
        orow[6] = __uint_as_float(f2tf32(oacc.w));
    }
}

// ---------------------------------------------------------------------------
// Launcher
// ---------------------------------------------------------------------------
extern "C" void kernel_launch(void* const* d_in, const int* in_sizes, int n_in,
                              void* d_out, int out_size)
{
    const float* x   = (const float*)d_in[0];
    const float* ctx = (const float*)d_in[1];
    const float* Wq  = (const float*)d_in[6];
    const float* bq  = (const float*)d_in[7];
    const float* Wk  = (const float*)d_in[8];
    const float* bk  = (const float*)d_in[9];
    const float* Wv  = (const float*)d_in[10];
    const float* bv  = (const float*)d_in[11];
    const float* Wo  = (const float*)d_in[12];
    const float* bo  = (const float*)d_in[13];
    const float* gq  = (const float*)d_in[14];
    const float* gk  = (const float*)d_in[15];
    float* out = (float*)d_out;

    float *xb, *wqb, *wob, *qb, *kb, *vb, *ob;
    cudaGetSymbolAddress((void**)&xb,  g_x);
    cudaGetSymbolAddress((void**)&wqb, g_wq);
    cudaGetSymbolAddress((void**)&wob, g_wo);
    cudaGetSymbolAddress((void**)&qb,  g_q);
    cudaGetSymbolAddress((void**)&kb,  g_k);
    cudaGetSymbolAddress((void**)&vb,  g_v);
    cudaGetSymbolAddress((void**)&ob,  g_o);

    cudaFuncSetAttribute(gemm_tc_kernel, cudaFuncAttributeMaxDynamicSharedMemorySize, GSMEM);
    const int lsmem = 2 * (BM * SROW + BN * SROW) * (int)sizeof(float);
    cudaFuncSetAttribute(gemm_tf32_kernel, cudaFuncAttributeMaxDynamicSharedMemorySize, lsmem);

    // Pre-round + K-permute inputs feeding the big GEMMs
    round_perm_kernel<<<2048, 256>>>(xb,  x,  (int)((size_t)L1TOK * DIMM / 8));
    round_perm_kernel<<<2048, 256>>>(wqb, Wq, (int)((size_t)DIMM  * DIMM / 8));
    round_perm_kernel<<<2048, 256>>>(wob, Wo, (int)((size_t)DIMM  * DIMM / 8));

    // Q projection: g_q = x @ Wq^T + bq
    {
        dim3 grid(DIMM / 128, (L1TOK + 255) / 256);
        gemm_tc_kernel<<<grid, 512, GSMEM>>>(xb, wqb, bq, qb, L1TOK);
    }
    // K / V projections (tiny)
    {
        dim3 grid(DIMM / BN, 1);
        gemm_tf32_kernel<<<grid, 256, lsmem>>>(ctx, Wk, bk, kb, LATOK, DIMM, KVD);
        gemm_tf32_kernel<<<grid, 256, lsmem>>>(ctx, Wv, bv, vb, LATOK, DIMM, KVD);
    }
    // RMSNorm
    rmsnorm_kernel<<<L1TOK, 256>>>(qb, gq);
    rmsnorm_kernel<<<LATOK, 256>>>(kb, gk);
    // Attention (writes tf32-rounded, K-permuted o)
    {
        dim3 grid(NFRAMES * NHEADS, (HWTOK + 15) / 16);
        attn_kernel<<<grid, 128>>>(qb, kb, vb, ob);
    }
    // Output projection: out = o @ Wo^T + bo
    {
        dim3 grid(DIMM / 128, (L1TOK + 255) / 256);
        gemm_tc_kernel<<<grid, 512, GSMEM>>>(ob, wob, bo, out, L1TOK);
    }
}

// round 8
// speedup vs baseline: 1.1162x; 1.0439x over previous
#include <cuda_runtime.h>
#include <cstdint>

// Problem constants (fixed by setup_inputs)
#define L1TOK   9360
#define DIMM    5120
#define KVD     1536
#define NHEADS  40
#define HDIM    128
#define LATOK   96
#define NFRAMES 6
#define HWTOK   1560

// Scratch (device globals: allocation-free)
// g_x, g_wq, g_wo, g_o hold tf32-rounded, K-PERMUTED data:
// within each group of 8 K-columns, order is {k0,k4,k1,k5,k2,k6,k3,k7}
__device__ float g_x [(size_t)L1TOK * DIMM];
__device__ float g_wq[(size_t)DIMM  * DIMM];
__device__ float g_wo[(size_t)DIMM  * DIMM];
__device__ float g_q [(size_t)L1TOK * DIMM];
__device__ float g_k [(size_t)LATOK * DIMM];
__device__ float g_v [(size_t)LATOK * DIMM];
__device__ float g_o [(size_t)L1TOK * DIMM];

// ---------------------------------------------------------------------------
// Helpers
// ---------------------------------------------------------------------------
__device__ __forceinline__ uint32_t f2tf32(float x) {
    uint32_t u;
    asm("cvt.rna.tf32.f32 %0, %1;" : "=r"(u) : "f"(x));
    return u;
}
__device__ __forceinline__ uint32_t smem_u32(const void* p) {
    uint32_t a;
    asm("{ .reg .u64 t; cvta.to.shared.u64 t, %1; cvt.u32.u64 %0, t; }" : "=r"(a) : "l"(p));
    return a;
}
__device__ __forceinline__ void mma_tf32(float* c, const uint32_t* a, uint32_t b0, uint32_t b1) {
    asm volatile(
        "mma.sync.aligned.m16n8k8.row.col.f32.tf32.tf32.f32 "
        "{%0,%1,%2,%3}, {%4,%5,%6,%7}, {%8,%9}, {%0,%1,%2,%3};\n"
        : "+f"(c[0]), "+f"(c[1]), "+f"(c[2]), "+f"(c[3])
        : "r"(a[0]), "r"(a[1]), "r"(a[2]), "r"(a[3]), "r"(b0), "r"(b1));
}
__device__ __forceinline__ void cp16(uint32_t dst, const float* src, bool pred) {
    asm volatile("cp.async.ca.shared.global [%0], [%1], 16, %2;"
                 :: "r"(dst), "l"(src), "r"(pred ? 16 : 0));
}
__device__ __forceinline__ void cp_commit() {
    asm volatile("cp.async.commit_group;" ::: "memory");
}
__device__ __forceinline__ void cp_wait1() {
    asm volatile("cp.async.wait_group 1;" ::: "memory");
}

// ---------------------------------------------------------------------------
// Big GEMM: C[M,5120] = A[M,5120] @ B[5120,5120]^T + bias
// A, B are tf32-rounded AND K-permuted (see above).
// CTA tile: 256(M) x 128(N), BK=32, 3-stage cp.async pipeline, 512 threads,
// 16 warps in 4(m) x 4(n), warp tile 64x32.
// A-fragments double-buffered in registers across the 4 ks steps.
// Stage rows padded to 40 floats (160 B) -> conflict-free LDS.64.
// ---------------------------------------------------------------------------
#define BKQ 32
#define SROWF 40
#define STG_A_F (256 * SROWF)         // 10240 floats (40960 B)
#define STG_B_F (128 * SROWF)         // 5120 floats  (20480 B)
#define STG_F   (STG_A_F + STG_B_F)   // 15360 floats (61440 B)
#define NSTG 3
#define GSMEM (NSTG * STG_F * 4)      // 184320 B
#define KTQ (DIMM / BKQ)              // 160

__global__ void __launch_bounds__(512, 1)
gemm_tc_kernel(const float* __restrict__ A, const float* __restrict__ B,
               const float* __restrict__ bias, float* __restrict__ C, int M)
{
    extern __shared__ float smp[];
    const uint32_t sbase = smem_u32(smp);
    const int t    = threadIdx.x;
    const int warp = t >> 5;
    const int lane = t & 31;
    const int wm   = warp >> 2;      // 0..3  (64 rows)
    const int wn   = warp & 3;       // 0..3  (32 cols)
    const int g    = lane >> 2;
    const int tg   = lane & 3;
    const int n0   = blockIdx.x * 128;
    const int m0   = blockIdx.y * 256;

    float acc[4][4][4];
    #pragma unroll
    for (int i = 0; i < 4; i++)
        #pragma unroll
        for (int j = 0; j < 4; j++)
            #pragma unroll
            for (int r = 0; r < 4; r++) acc[i][j][r] = 0.f;

    // --- hoisted fill coordinates (loop-invariant) ---
    int  rA[4], cA[4]; bool pA[4];
    #pragma unroll
    for (int i = 0; i < 4; i++) {
        int id = t + i * 512;
        rA[i] = id >> 3; cA[i] = id & 7;
        pA[i] = (m0 + rA[i]) < M;
    }
    int rB[2], cB[2];
    #pragma unroll
    for (int i = 0; i < 2; i++) {
        int id = t + i * 512;
        rB[i] = id >> 3; cB[i] = id & 7;
    }

    auto fill = [&](int stage, int kt) {
        const int k0 = kt * BKQ;
        const uint32_t sb = sbase + stage * (STG_F * 4);
        #pragma unroll
        for (int i = 0; i < 4; i++)
            cp16(sb + rA[i] * 160 + cA[i] * 16,
                 A + (size_t)(m0 + rA[i]) * DIMM + k0 + cA[i] * 4, pA[i]);
        #pragma unroll
        for (int i = 0; i < 2; i++)
            cp16(sb + STG_A_F * 4 + rB[i] * 160 + cB[i] * 16,
                 B + (size_t)(n0 + rB[i]) * DIMM + k0 + cB[i] * 4, true);
    };

    // prologue: stages 0,1
    fill(0, 0); cp_commit();
    fill(1, 1); cp_commit();

    const int aoff0 = (wm * 64 + g) * SROWF + 2 * tg;
    const int boff0 = (wn * 32 + g) * SROWF + 2 * tg;

    uint32_t af[2][4][4];
    int buf = 0;

    for (int kt = 0; kt < KTQ; ++kt) {
        cp_wait1();
        __syncthreads();      // stage kt visible; all reads of stage kt-1 done

        if (kt + 2 < KTQ) fill(buf == 0 ? 2 : buf - 1, kt + 2);
        cp_commit();

        const float* stA = smp + buf * STG_F + aoff0;
        const float* stB = smp + buf * STG_F + STG_A_F + boff0;

        // load ks=0 A-fragments
        #pragma unroll
        for (int mt = 0; mt < 4; ++mt) {
            const float* p = stA + mt * (16 * SROWF);
            float2 lo = *(const float2*)p;
            float2 hi = *(const float2*)(p + 8 * SROWF);
            af[0][mt][0] = __float_as_uint(lo.x);
            af[0][mt][1] = __float_as_uint(hi.x);
            af[0][mt][2] = __float_as_uint(lo.y);
            af[0][mt][3] = __float_as_uint(hi.y);
        }

        #pragma unroll
        for (int ks = 0; ks < 4; ++ks) {
            const int cur = ks & 1;
            if (ks < 3) {   // prefetch A-fragments for ks+1 into the other buffer
                const int kk = (ks + 1) * 8;
                #pragma unroll
                for (int mt = 0; mt < 4; ++mt) {
                    const float* p = stA + mt * (16 * SROWF) + kk;
                    float2 lo = *(const float2*)p;
                    float2 hi = *(const float2*)(p + 8 * SROWF);
                    af[cur ^ 1][mt][0] = __float_as_uint(lo.x);
                    af[cur ^ 1][mt][1] = __float_as_uint(hi.x);
                    af[cur ^ 1][mt][2] = __float_as_uint(lo.y);
                    af[cur ^ 1][mt][3] = __float_as_uint(hi.y);
                }
            }
            const int kk = ks * 8;
            #pragma unroll
            for (int nt = 0; nt < 4; ++nt) {
                float2 bb = *(const float2*)(stB + nt * (8 * SROWF) + kk);
                uint32_t b0 = __float_as_uint(bb.x);
                uint32_t b1 = __float_as_uint(bb.y);
                #pragma unroll
                for (int mt = 0; mt < 4; ++mt)
                    mma_tf32(acc[mt][nt], af[cur][mt], b0, b1);
            }
        }

        if (++buf == NSTG) buf = 0;
    }

    // --- epilogue ---
    #pragma unroll
    for (int mt = 0; mt < 4; ++mt) {
        const int r0 = m0 + wm * 64 + mt * 16 + g;
        #pragma unroll
        for (int nt = 0; nt < 4; ++nt) {
            const int c0 = n0 + wn * 32 + nt * 8 + tg * 2;
            const float b0v = bias[c0];
            const float b1v = bias[c0 + 1];
            if (r0 < M) {
                float2 o0 = { acc[mt][nt][0] + b0v, acc[mt][nt][1] + b1v };
                *(float2*)(C + (size_t)r0 * DIMM + c0) = o0;
            }
            if (r0 + 8 < M) {
                float2 o1 = { acc[mt][nt][2] + b0v, acc[mt][nt][3] + b1v };
                *(float2*)(C + (size_t)(r0 + 8) * DIMM + c0) = o1;
            }
        }
    }
}

// ---------------------------------------------------------------------------
// Pre-round + K-permute kernel:
// per 8-float group: out = {k0,k4,k1,k5,k2,k6,k3,k7}, all tf32-rounded.
// ---------------------------------------------------------------------------
__global__ void __launch_bounds__(256)
round_perm_kernel(float* __restrict__ dst, const float* __restrict__ src, int n8)
{
    const int stride = gridDim.x * 256;
    for (int i = blockIdx.x * 256 + threadIdx.x; i < n8; i += stride) {
        float4 a = ((const float4*)src)[2 * i];
        float4 b = ((const float4*)src)[2 * i + 1];
        uint4 o0 = { f2tf32(a.x), f2tf32(b.x), f2tf32(a.y), f2tf32(b.y) };
        uint4 o1 = { f2tf32(a.z), f2tf32(b.z), f2tf32(a.w), f2tf32(b.w) };
        ((uint4*)dst)[2 * i]     = o0;
        ((uint4*)dst)[2 * i + 1] = o1;
    }
}

// ---------------------------------------------------------------------------
// Legacy TF32 GEMM for small K/V projections (M=96): C = A @ B^T + bias
// ---------------------------------------------------------------------------
__device__ __forceinline__ void mma_tf32b(float* c, const uint32_t* a, const uint32_t* b) {
    asm volatile(
        "mma.sync.aligned.m16n8k8.row.col.f32.tf32.tf32.f32 "
        "{%0,%1,%2,%3}, {%4,%5,%6,%7}, {%8,%9}, {%0,%1,%2,%3};\n"
        : "+f"(c[0]), "+f"(c[1]), "+f"(c[2]), "+f"(c[3])
        : "r"(a[0]), "r"(a[1]), "r"(a[2]), "r"(a[3]), "r"(b[0]), "r"(b[1]));
}
#define BM 128
#define BN 128
#define SROW 36

__global__ void __launch_bounds__(256, 1)
gemm_tf32_kernel(const float* __restrict__ A, const float* __restrict__ B,
                 const float* __restrict__ bias, float* __restrict__ C,
                 int M, int N, int K)
{
    extern __shared__ float fsm[];
    float* sA = fsm;
    float* sB = fsm + 2 * BM * SROW;
    const int t = threadIdx.x, warp = t >> 5, lane = t & 31;
    const int wm = warp >> 2, wn = warp & 3, g = lane >> 2, tg = lane & 3;
    const int row0 = blockIdx.y * BM, col0 = blockIdx.x * BN;

    float acc[4][4][4];
    #pragma unroll
    for (int i = 0; i < 4; i++) for (int j = 0; j < 4; j++) for (int r = 0; r < 4; r++) acc[i][j][r] = 0.f;
    float4 rA[4], rB[4];
    const int KTl = K / 32;

    auto LDG = [&](int kt) {
        const int k0 = kt * 32;
        #pragma unroll
        for (int i = 0; i < 4; i++) {
            int id = t + i * 256, r = id >> 3, c4 = id & 7;
            int ga = row0 + r;
            rA[i] = (ga < M) ? *(const float4*)(A + (size_t)ga * K + k0 + c4 * 4) : make_float4(0.f,0.f,0.f,0.f);
            rB[i] = *(const float4*)(B + (size_t)(col0 + r) * K + k0 + c4 * 4);
        }
    };
    auto STS = [&](int buf) {
        float* dA = sA + buf * BM * SROW;
        float* dB = sB + buf * BN * SROW;
        #pragma unroll
        for (int i = 0; i < 4; i++) {
            int id = t + i * 256, r = id >> 3, c4 = id & 7;
            uint4 ua = { f2tf32(rA[i].x), f2tf32(rA[i].y), f2tf32(rA[i].z), f2tf32(rA[i].w) };
            *(uint4*)(dA + r * SROW + c4 * 4) = ua;
            uint4 ub = { f2tf32(rB[i].x), f2tf32(rB[i].y), f2tf32(rB[i].z), f2tf32(rB[i].w) };
            *(uint4*)(dB + r * SROW + c4 * 4) = ub;
        }
    };

    LDG(0); STS(0); __syncthreads();
    int buf = 0;
    for (int kt = 0; kt < KTl; ++kt) {
        if (kt + 1 < KTl) LDG(kt + 1);
        const uint32_t* uA = (const uint32_t*)(sA + buf * BM * SROW);
        const uint32_t* uB = (const uint32_t*)(sB + buf * BN * SROW);
        #pragma unroll
        for (int ks = 0; ks < 4; ++ks) {
            const int kk = ks * 8;
            uint32_t af[4][4], bf[4][2];
            #pragma unroll
            for (int mt = 0; mt < 4; ++mt) {
                int r = wm * 64 + mt * 16 + g;
                af[mt][0] = uA[r * SROW + kk + tg];
                af[mt][1] = uA[(r + 8) * SROW + kk + tg];
                af[mt][2] = uA[r * SROW + kk + tg + 4];
                af[mt][3] = uA[(r + 8) * SROW + kk + tg + 4];
            }
            #pragma unroll
            for (int nt = 0; nt < 4; ++nt) {
                int n = wn * 32 + nt * 8 + g;
                bf[nt][0] = uB[n * SROW + kk + tg];
                bf[nt][1] = uB[n * SROW + kk + tg + 4];
            }
            #pragma unroll
            for (int mt = 0; mt < 4; ++mt)
                #pragma unroll
                for (int nt = 0; nt < 4; ++nt)
                    mma_tf32b(acc[mt][nt], af[mt], bf[nt]);
        }
        if (kt + 1 < KTl) STS(buf ^ 1);
        __syncthreads();
        buf ^= 1;
    }
    #pragma unroll
    for (int mt = 0; mt < 4; ++mt) {
        int r0 = row0 + wm * 64 + mt * 16 + g;
        #pragma unroll
        for (int nt = 0; nt < 4; ++nt) {
            int c0 = col0 + wn * 32 + nt * 8 + tg * 2;
            float b0v = bias[c0], b1v = bias[c0 + 1];
            if (r0 < M) {
                C[(size_t)r0 * N + c0]     = acc[mt][nt][0] + b0v;
                C[(size_t)r0 * N + c0 + 1] = acc[mt][nt][1] + b1v;
            }
            if (r0 + 8 < M) {
                C[(size_t)(r0 + 8) * N + c0]     = acc[mt][nt][2] + b0v;
                C[(size_t)(r0 + 8) * N + c0 + 1] = acc[mt][nt][3] + b1v;
            }
        }
    }
}

// ---------------------------------------------------------------------------
// RMSNorm (rows of 5120)
// ---------------------------------------------------------------------------
__global__ void __launch_bounds__(256)
rmsnorm_kernel(float* __restrict__ buf, const float* __restrict__ gvec)
{
    const int row = blockIdx.x, t = threadIdx.x, lane = t & 31, warp = t >> 5;
    float4* p4 = (float4*)(buf + (size_t)row * DIMM);
    const float4* g4 = (const float4*)gvec;
    float4 v[5]; float ss = 0.f;
    #pragma unroll
    for (int i = 0; i < 5; i++) {
        v[i] = p4[t + i * 256];
        ss += v[i].x*v[i].x + v[i].y*v[i].y + v[i].z*v[i].z + v[i].w*v[i].w;
    }
    #pragma unroll
    for (int off = 16; off > 0; off >>= 1) ss += __shfl_xor_sync(0xffffffffu, ss, off);
    __shared__ float red[8]; __shared__ float stot;
    if (lane == 0) red[warp] = ss;
    __syncthreads();
    if (t < 8) {
        float tot = red[t];
        #pragma unroll
        for (int off = 4; off > 0; off >>= 1) tot += __shfl_xor_sync(0xffu, tot, off);
        if (t == 0) stot = tot;
    }
    __syncthreads();
    const float inv = rsqrtf(stot / (float)DIMM + 1e-6f);
    #pragma unroll
    for (int i = 0; i < 5; i++) {
        float4 gv = g4[t + i * 256];
        float4 o = { v[i].x*inv*gv.x, v[i].y*inv*gv.y, v[i].z*inv*gv.z, v[i].w*inv*gv.w };
        p4[t + i * 256] = o;
    }
}

// ---------------------------------------------------------------------------
// Attention: per (frame, head), 16 keys.
// Output written tf32-rounded AND K-permuted (feeds O-projection as A).
// ---------------------------------------------------------------------------
#define SKPAD 132
__global__ void __launch_bounds__(128)
attn_kernel(const float* __restrict__ q, const float* __restrict__ k,
            const float* __restrict__ v, float* __restrict__ o)
{
    const int fh = blockIdx.x, f = fh / NHEADS, h = fh % NHEADS;
    __shared__ float sk[16][SKPAD];
    __shared__ float sv[16][SKPAD];
    const int t = threadIdx.x;
    #pragma unroll
    for (int i = 0; i < 4; i++) {
        int id = t + i * 128, j = id >> 5, c4 = id & 31;
        size_t goff = ((size_t)(f * 16 + j)) * DIMM + h * HDIM + c4 * 4;
        *(float4*)(&sk[j][c4 * 4]) = *(const float4*)(k + goff);
        *(float4*)(&sv[j][c4 * 4]) = *(const float4*)(v + goff);
    }
    __syncthreads();
    const int warp = t >> 5, lane = t & 31;
    const float scale = 0.08838834764831844f;
    #pragma unroll
    for (int rr = 0; rr < 4; ++rr) {
        const int pos = blockIdx.y * 16 + warp * 4 + rr;
        if (pos >= HWTOK) break;
        const float4* q4 = (const float4*)(q + ((size_t)(f * HWTOK + pos)) * DIMM + h * HDIM);
        float logit = -1e30f;
        if (lane < 16) {
            float s = 0.f;
            #pragma unroll
            for (int c = 0; c < 32; c++) {
                float4 a = q4[c];
                float4 b = *(const float4*)(&sk[lane][c * 4]);
                s += a.x*b.x + a.y*b.y + a.z*b.z + a.w*b.w;
            }
            logit = s * scale;
        }
        float m = logit;
        #pragma unroll
        for (int off = 8; off > 0; off >>= 1) m = fmaxf(m, __shfl_xor_sync(0xffffffffu, m, off, 16));
        float e = (lane < 16) ? expf(logit - m) : 0.f;
        float ssum = e;
        #pragma unroll
        for (int off = 8; off > 0; off >>= 1) ssum += __shfl_xor_sync(0xffffffffu, ssum, off, 16);
        float att = (lane < 16) ? (e / ssum) : 0.f;
        float4 oacc = make_float4(0.f, 0.f, 0.f, 0.f);
        #pragma unroll
        for (int j = 0; j < 16; j++) {
            float aj = __shfl_sync(0xffffffffu, att, j);
            float4 vv = *(const float4*)(&sv[j][lane * 4]);
            oacc.x += aj*vv.x; oacc.y += aj*vv.y; oacc.z += aj*vv.z; oacc.w += aj*vv.w;
        }
        // Store tf32-rounded, K-permuted: old col 4L+j -> group (L>>1)*8, slot 2*j + (L&1)
        float* orow = o + ((size_t)(f * HWTOK + pos)) * DIMM + h * HDIM + (lane >> 1) * 8 + (lane & 1);
        orow[0] = __uint_as_float(f2tf32(oacc.x));
        orow[2] = __uint_as_float(f2tf32(oacc.y));
        orow[4] = __uint_as_float(f2tf32(oacc.z));
        orow[6] = __uint_as_float(f2tf32(oacc.w));
    }
}

// ---------------------------------------------------------------------------
// Launcher
// ---------------------------------------------------------------------------
extern "C" void kernel_launch(void* const* d_in, const int* in_sizes, int n_in,
                              void* d_out, int out_size)
{
    const float* x   = (const float*)d_in[0];
    const float* ctx = (const float*)d_in[1];
    const float* Wq  = (const float*)d_in[6];
    const float* bq  = (const float*)d_in[7];
    const float* Wk  = (const float*)d_in[8];
    const float* bk  = (const float*)d_in[9];
    const float* Wv  = (const float*)d_in[10];
    const float* bv  = (const float*)d_in[11];
    const float* Wo  = (const float*)d_in[12];
    const float* bo  = (const float*)d_in[13];
    const float* gq  = (const float*)d_in[14];
    const float* gk  = (const float*)d_in[15];
    float* out = (float*)d_out;

    float *xb, *wqb, *wob, *qb, *kb, *vb, *ob;
    cudaGetSymbolAddress((void**)&xb,  g_x);
    cudaGetSymbolAddress((void**)&wqb, g_wq);
    cudaGetSymbolAddress((void**)&wob, g_wo);
    cudaGetSymbolAddress((void**)&qb,  g_q);
    cudaGetSymbolAddress((void**)&kb,  g_k);
    cudaGetSymbolAddress((void**)&vb,  g_v);
    cudaGetSymbolAddress((void**)&ob,  g_o);

    cudaFuncSetAttribute(gemm_tc_kernel, cudaFuncAttributeMaxDynamicSharedMemorySize, GSMEM);
    const int lsmem = 2 * (BM * SROW + BN * SROW) * (int)sizeof(float);
    cudaFuncSetAttribute(gemm_tf32_kernel, cudaFuncAttributeMaxDynamicSharedMemorySize, lsmem);

    // Pre-round + K-permute inputs feeding the big GEMMs
    round_perm_kernel<<<2048, 256>>>(xb,  x,  (int)((size_t)L1TOK * DIMM / 8));
    round_perm_kernel<<<2048, 256>>>(wqb, Wq, (int)((size_t)DIMM  * DIMM / 8));
    round_perm_kernel<<<2048, 256>>>(wob, Wo, (int)((size_t)DIMM  * DIMM / 8));

    // Q projection: g_q = x @ Wq^T + bq
    {
        dim3 grid(DIMM / 128, (L1TOK + 255) / 256);
        gemm_tc_kernel<<<grid, 512, GSMEM>>>(xb, wqb, bq, qb, L1TOK);
    }
    // K / V projections (tiny)
    {
        dim3 grid(DIMM / BN, 1);
        gemm_tf32_kernel<<<grid, 256, lsmem>>>(ctx, Wk, bk, kb, LATOK, DIMM, KVD);
        gemm_tf32_kernel<<<grid, 256, lsmem>>>(ctx, Wv, bv, vb, LATOK, DIMM, KVD);
    }
    // RMSNorm
    rmsnorm_kernel<<<L1TOK, 256>>>(qb, gq);
    rmsnorm_kernel<<<LATOK, 256>>>(kb, gk);
    // Attention (writes tf32-rounded, K-permuted o)
    {
        dim3 grid(NFRAMES * NHEADS, (HWTOK + 15) / 16);
        attn_kernel<<<grid, 128>>>(qb, kb, vb, ob);
    }
    // Output projection: out = o @ Wo^T + bo
    {
        dim3 grid(DIMM / 128, (L1TOK + 255) / 256);
        gemm_tc_kernel<<<grid, 512, GSMEM>>>(ob, wob, bo, out, L1TOK);
    }
}

// round 10
// speedup vs baseline: 1.1455x; 1.0263x over previous
#include <cuda_runtime.h>
#include <cstdint>

// Problem constants (fixed by setup_inputs)
#define L1TOK   9360
#define DIMM    5120
#define KVD     1536
#define NHEADS  40
#define HDIM    128
#define LATOK   96
#define NFRAMES 6
#define HWTOK   1560

// Scratch (device globals: allocation-free)
// g_x, g_wq, g_wo, g_o hold tf32-rounded, K-PERMUTED data:
// within each group of 8 K-columns, order is {k0,k4,k1,k5,k2,k6,k3,k7}
__device__ float g_x [(size_t)L1TOK * DIMM];
__device__ float g_wq[(size_t)DIMM  * DIMM];
__device__ float g_wo[(size_t)DIMM  * DIMM];
__device__ float g_q [(size_t)L1TOK * DIMM];
__device__ float g_k [(size_t)LATOK * DIMM];
__device__ float g_v [(size_t)LATOK * DIMM];
__device__ float g_o [(size_t)L1TOK * DIMM];

// ---------------------------------------------------------------------------
// Helpers
// ---------------------------------------------------------------------------
__device__ __forceinline__ uint32_t f2tf32(float x) {
    uint32_t u;
    asm("cvt.rna.tf32.f32 %0, %1;" : "=r"(u) : "f"(x));
    return u;
}
__device__ __forceinline__ uint32_t smem_u32(const void* p) {
    uint32_t a;
    asm("{ .reg .u64 t; cvta.to.shared.u64 t, %1; cvt.u32.u64 %0, t; }" : "=r"(a) : "l"(p));
    return a;
}
__device__ __forceinline__ void mma_tf32(float* c, const uint32_t* a, uint32_t b0, uint32_t b1) {
    asm volatile(
        "mma.sync.aligned.m16n8k8.row.col.f32.tf32.tf32.f32 "
        "{%0,%1,%2,%3}, {%4,%5,%6,%7}, {%8,%9}, {%0,%1,%2,%3};\n"
        : "+f"(c[0]), "+f"(c[1]), "+f"(c[2]), "+f"(c[3])
        : "r"(a[0]), "r"(a[1]), "r"(a[2]), "r"(a[3]), "r"(b0), "r"(b1));
}
__device__ __forceinline__ void cp16(uint32_t dst, const float* src, bool pred) {
    asm volatile("cp.async.ca.shared.global [%0], [%1], 16, %2;"
                 :: "r"(dst), "l"(src), "r"(pred ? 16 : 0));
}
__device__ __forceinline__ void cp_commit() {
    asm volatile("cp.async.commit_group;" ::: "memory");
}
__device__ __forceinline__ void cp_wait1() {
    asm volatile("cp.async.wait_group 1;" ::: "memory");
}

// ---------------------------------------------------------------------------
// Big GEMM: C[M,5120] = A[M,5120] @ B[5120,5120]^T + bias
// A, B are tf32-rounded AND K-permuted (see above).
// CTA tile: 256(M) x 128(N), BK=32, 3-stage cp.async pipeline, 256 threads,
// 8 warps in 4(m) x 2(n), warp tile 64x64.
// BOTH A and B fragments double-buffered in registers across the 4 ks steps.
// Stage rows padded to 40 floats (160 B) -> conflict-free LDS.64.
// ---------------------------------------------------------------------------
#define BKQ 32
#define SROWF 40
#define STG_A_F (256 * SROWF)         // 10240 floats (40960 B)
#define STG_B_F (128 * SROWF)         // 5120 floats  (20480 B)
#define STG_F   (STG_A_F + STG_B_F)   // 15360 floats (61440 B)
#define NSTG 3
#define GSMEM (NSTG * STG_F * 4)      // 184320 B
#define KTQ (DIMM / BKQ)              // 160

__global__ void __launch_bounds__(256, 1)
gemm_tc_kernel(const float* __restrict__ A, const float* __restrict__ B,
               const float* __restrict__ bias, float* __restrict__ C, int M)
{
    extern __shared__ float smp[];
    const uint32_t sbase = smem_u32(smp);
    const int t    = threadIdx.x;
    const int warp = t >> 5;
    const int lane = t & 31;
    const int wm   = warp >> 1;      // 0..3  (64 rows)
    const int wn   = warp & 1;       // 0..1  (64 cols)
    const int g    = lane >> 2;
    const int tg   = lane & 3;
    const int n0   = blockIdx.x * 128;
    const int m0   = blockIdx.y * 256;

    float acc[4][8][4];
    #pragma unroll
    for (int i = 0; i < 4; i++)
        #pragma unroll
        for (int j = 0; j < 8; j++)
            #pragma unroll
            for (int r = 0; r < 4; r++) acc[i][j][r] = 0.f;

    // --- fill state: advancing base pointers + immediate offsets ---
    const int rr0 = t >> 3;           // base row (A: +32 per chunk i; B same)
    const int cc0 = t & 7;            // float4 column within the 32-float row
    const float* pa0 = A + (size_t)(m0 + rr0) * DIMM + cc0 * 4;
    const float* pb0 = B + (size_t)(n0 + rr0) * DIMM + cc0 * 4;
    const uint32_t da0 = rr0 * 160 + cc0 * 16;
    const uint32_t db0 = STG_A_F * 4 + rr0 * 160 + cc0 * 16;
    const int mrow0 = m0 + rr0;

    auto fill = [&](int stage) {
        const uint32_t sb = sbase + stage * (STG_F * 4);
        #pragma unroll
        for (int i = 0; i < 8; i++)    // A: 256 rows, this thread rows rr0+32i
            cp16(sb + da0 + i * 5120,
                 pa0 + (size_t)i * 32 * DIMM, (mrow0 + 32 * i) < M);
        #pragma unroll
        for (int i = 0; i < 4; i++)    // B: 128 rows
            cp16(sb + db0 + i * 5120,
                 pb0 + (size_t)i * 32 * DIMM, true);
        pa0 += BKQ;
        pb0 += BKQ;
    };

    // prologue: stages 0,1
    fill(0); cp_commit();
    fill(1); cp_commit();

    const int aoff0 = (wm * 64 + g) * SROWF + 2 * tg;
    const int boff0 = STG_A_F + (wn * 64 + g) * SROWF + 2 * tg;

    uint32_t af[2][4][4];
    uint32_t bf[2][8][2];
    int buf = 0;

    for (int kt = 0; kt < KTQ; ++kt) {
        cp_wait1();
        __syncthreads();      // stage kt visible; all reads of stage kt-1 done

        if (kt + 2 < KTQ) fill(buf == 0 ? 2 : buf - 1);
        cp_commit();

        const float* stA = smp + buf * STG_F + aoff0;
        const float* stB = smp + buf * STG_F + boff0;

        // load ks=0 fragments
        #pragma unroll
        for (int mt = 0; mt < 4; ++mt) {
            const float* p = stA + mt * (16 * SROWF);
            float2 lo = *(const float2*)p;
            float2 hi = *(const float2*)(p + 8 * SROWF);
            af[0][mt][0] = __float_as_uint(lo.x);
            af[0][mt][1] = __float_as_uint(hi.x);
            af[0][mt][2] = __float_as_uint(lo.y);
            af[0][mt][3] = __float_as_uint(hi.y);
        }
        #pragma unroll
        for (int nt = 0; nt < 8; ++nt) {
            float2 bb = *(const float2*)(stB + nt * (8 * SROWF));
            bf[0][nt][0] = __float_as_uint(bb.x);
            bf[0][nt][1] = __float_as_uint(bb.y);
        }

        #pragma unroll
        for (int ks = 0; ks < 4; ++ks) {
            const int cur = ks & 1;
            if (ks < 3) {   // prefetch fragments for ks+1 into the other buffer
                const int kk = (ks + 1) * 8;
                #pragma unroll
                for (int mt = 0; mt < 4; ++mt) {
                    const float* p = stA + mt * (16 * SROWF) + kk;
                    float2 lo = *(const float2*)p;
                    float2 hi = *(const float2*)(p + 8 * SROWF);
                    af[cur ^ 1][mt][0] = __float_as_uint(lo.x);
                    af[cur ^ 1][mt][1] = __float_as_uint(hi.x);
                    af[cur ^ 1][mt][2] = __float_as_uint(lo.y);
                    af[cur ^ 1][mt][3] = __float_as_uint(hi.y);
                }
                #pragma unroll
                for (int nt = 0; nt < 8; ++nt) {
                    float2 bb = *(const float2*)(stB + nt * (8 * SROWF) + kk);
                    bf[cur ^ 1][nt][0] = __float_as_uint(bb.x);
                    bf[cur ^ 1][nt][1] = __float_as_uint(bb.y);
                }
            }
            #pragma unroll
            for (int nt = 0; nt < 8; ++nt)
                #pragma unroll
                for (int mt = 0; mt < 4; ++mt)
                    mma_tf32(acc[mt][nt], af[cur][mt], bf[cur][nt][0], bf[cur][nt][1]);
        }

        if (++buf == NSTG) buf = 0;
    }

    // --- epilogue ---
    #pragma unroll
    for (int mt = 0; mt < 4; ++mt) {
        const int r0 = m0 + wm * 64 + mt * 16 + g;
        #pragma unroll
        for (int nt = 0; nt < 8; ++nt) {
            const int c0 = n0 + wn * 64 + nt * 8 + tg * 2;
            const float b0v = bias[c0];
            const float b1v = bias[c0 + 1];
            if (r0 < M) {
                float2 o0 = { acc[mt][nt][0] + b0v, acc[mt][nt][1] + b1v };
                *(float2*)(C + (size_t)r0 * DIMM + c0) = o0;
            }
            if (r0 + 8 < M) {
                float2 o1 = { acc[mt][nt][2] + b0v, acc[mt][nt][3] + b1v };
                *(float2*)(C + (size_t)(r0 + 8) * DIMM + c0) = o1;
            }
        }
    }
}

// ---------------------------------------------------------------------------
// Pre-round + K-permute kernel:
// per 8-float group: out = {k0,k4,k1,k5,k2,k6,k3,k7}, all tf32-rounded.
// ---------------------------------------------------------------------------
__global__ void __launch_bounds__(256)
round_perm_kernel(float* __restrict__ dst, const float* __restrict__ src, int n8)
{
    const int stride = gridDim.x * 256;
    for (int i = blockIdx.x * 256 + threadIdx.x; i < n8; i += stride) {
        float4 a = ((const float4*)src)[2 * i];
        float4 b = ((const float4*)src)[2 * i + 1];
        uint4 o0 = { f2tf32(a.x), f2tf32(b.x), f2tf32(a.y), f2tf32(b.y) };
        uint4 o1 = { f2tf32(a.z), f2tf32(b.z), f2tf32(a.w), f2tf32(b.w) };
        ((uint4*)dst)[2 * i]     = o0;
        ((uint4*)dst)[2 * i + 1] = o1;
    }
}

// ---------------------------------------------------------------------------
// Legacy TF32 GEMM for small K/V projections (M=96): C = A @ B^T + bias
// ---------------------------------------------------------------------------
__device__ __forceinline__ void mma_tf32b(float* c, const uint32_t* a, const uint32_t* b) {
    asm volatile(
        "mma.sync.aligned.m16n8k8.row.col.f32.tf32.tf32.f32 "
        "{%0,%1,%2,%3}, {%4,%5,%6,%7}, {%8,%9}, {%0,%1,%2,%3};\n"
        : "+f"(c[0]), "+f"(c[1]), "+f"(c[2]), "+f"(c[3])
        : "r"(a[0]), "r"(a[1]), "r"(a[2]), "r"(a[3]), "r"(b[0]), "r"(b[1]));
}
#define BM 128
#define BN 128
#define SROW 36

__global__ void __launch_bounds__(256, 1)
gemm_tf32_kernel(const float* __restrict__ A, const float* __restrict__ B,
                 const float* __restrict__ bias, float* __restrict__ C,
                 int M, int N, int K)
{
    extern __shared__ float fsm[];
    float* sA = fsm;
    float* sB = fsm + 2 * BM * SROW;
    const int t = threadIdx.x, warp = t >> 5, lane = t & 31;
    const int wm = warp >> 2, wn = warp & 3, g = lane >> 2, tg = lane & 3;
    const int row0 = blockIdx.y * BM, col0 = blockIdx.x * BN;

    float acc[4][4][4];
    #pragma unroll
    for (int i = 0; i < 4; i++) for (int j = 0; j < 4; j++) for (int r = 0; r < 4; r++) acc[i][j][r] = 0.f;
    float4 rA[4], rB[4];
    const int KTl = K / 32;

    auto LDG = [&](int kt) {
        const int k0 = kt * 32;
        #pragma unroll
        for (int i = 0; i < 4; i++) {
            int id = t + i * 256, r = id >> 3, c4 = id & 7;
            int ga = row0 + r;
            rA[i] = (ga < M) ? *(const float4*)(A + (size_t)ga * K + k0 + c4 * 4) : make_float4(0.f,0.f,0.f,0.f);
            rB[i] = *(const float4*)(B + (size_t)(col0 + r) * K + k0 + c4 * 4);
        }
    };
    auto STS = [&](int buf) {
        float* dA = sA + buf * BM * SROW;
        float* dB = sB + buf * BN * SROW;
        #pragma unroll
        for (int i = 0; i < 4; i++) {
            int id = t + i * 256, r = id >> 3, c4 = id & 7;
            uint4 ua = { f2tf32(rA[i].x), f2tf32(rA[i].y), f2tf32(rA[i].z), f2tf32(rA[i].w) };
            *(uint4*)(dA + r * SROW + c4 * 4) = ua;
            uint4 ub = { f2tf32(rB[i].x), f2tf32(rB[i].y), f2tf32(rB[i].z), f2tf32(rB[i].w) };
            *(uint4*)(dB + r * SROW + c4 * 4) = ub;
        }
    };

    LDG(0); STS(0); __syncthreads();
    int buf = 0;
    for (int kt = 0; kt < KTl; ++kt) {
        if (kt + 1 < KTl) LDG(kt + 1);
        const uint32_t* uA = (const uint32_t*)(sA + buf * BM * SROW);
        const uint32_t* uB = (const uint32_t*)(sB + buf * BN * SROW);
        #pragma unroll
        for (int ks = 0; ks < 4; ++ks) {
            const int kk = ks * 8;
            uint32_t af[4][4], bf[4][2];
            #pragma unroll
            for (int mt = 0; mt < 4; ++mt) {
                int r = wm * 64 + mt * 16 + g;
                af[mt][0] = uA[r * SROW + kk + tg];
                af[mt][1] = uA[(r + 8) * SROW + kk + tg];
                af[mt][2] = uA[r * SROW + kk + tg + 4];
                af[mt][3] = uA[(r + 8) * SROW + kk + tg + 4];
            }
            #pragma unroll
            for (int nt = 0; nt < 4; ++nt) {
                int n = wn * 32 + nt * 8 + g;
                bf[nt][0] = uB[n * SROW + kk + tg];
                bf[nt][1] = uB[n * SROW + kk + tg + 4];
            }
            #pragma unroll
            for (int mt = 0; mt < 4; ++mt)
                #pragma unroll
                for (int nt = 0; nt < 4; ++nt)
                    mma_tf32b(acc[mt][nt], af[mt], bf[nt]);
        }
        if (kt + 1 < KTl) STS(buf ^ 1);
        __syncthreads();
        buf ^= 1;
    }
    #pragma unroll
    for (int mt = 0; mt < 4; ++mt) {
        int r0 = row0 + wm * 64 + mt * 16 + g;
        #pragma unroll
        for (int nt = 0; nt < 4; ++nt) {
            int c0 = col0 + wn * 32 + nt * 8 + tg * 2;
            float b0v = bias[c0], b1v = bias[c0 + 1];
            if (r0 < M) {
                C[(size_t)r0 * N + c0]     = acc[mt][nt][0] + b0v;
                C[(size_t)r0 * N + c0 + 1] = acc[mt][nt][1] + b1v;
            }
            if (r0 + 8 < M) {
                C[(size_t)(r0 + 8) * N + c0]     = acc[mt][nt][2] + b0v;
                C[(size_t)(r0 + 8) * N + c0 + 1] = acc[mt][nt][3] + b1v;
            }
        }
    }
}

// ---------------------------------------------------------------------------
// RMSNorm (rows of 5120)
// ---------------------------------------------------------------------------
__global__ void __launch_bounds__(256)
rmsnorm_kernel(float* __restrict__ buf, const float* __restrict__ gvec)
{
    const int row = blockIdx.x, t = threadIdx.x, lane = t & 31, warp = t >> 5;
    float4* p4 = (float4*)(buf + (size_t)row * DIMM);
    const float4* g4 = (const float4*)gvec;
    float4 v[5]; float ss = 0.f;
    #pragma unroll
    for (int i = 0; i < 5; i++) {
        v[i] = p4[t + i * 256];
        ss += v[i].x*v[i].x + v[i].y*v[i].y + v[i].z*v[i].z + v[i].w*v[i].w;
    }
    #pragma unroll
    for (int off = 16; off > 0; off >>= 1) ss += __shfl_xor_sync(0xffffffffu, ss, off);
    __shared__ float red[8]; __shared__ float stot;
    if (lane == 0) red[warp] = ss;
    __syncthreads();
    if (t < 8) {
        float tot = red[t];
        #pragma unroll
        for (int off = 4; off > 0; off >>= 1) tot += __shfl_xor_sync(0xffu, tot, off);
        if (t == 0) stot = tot;
    }
    __syncthreads();
    const float inv = rsqrtf(stot / (float)DIMM + 1e-6f);
    #pragma unroll
    for (int i = 0; i < 5; i++) {
        float4 gv = g4[t + i * 256];
        float4 o = { v[i].x*inv*gv.x, v[i].y*inv*gv.y, v[i].z*inv*gv.z, v[i].w*inv*gv.w };
        p4[t + i * 256] = o;
    }
}

// ---------------------------------------------------------------------------
// Attention: per (frame, head), 16 keys.
// Output written tf32-rounded AND K-permuted (feeds O-projection as A).
// ---------------------------------------------------------------------------
#define SKPAD 132
__global__ void __launch_bounds__(128)
attn_kernel(const float* __restrict__ q, const float* __restrict__ k,
            const float* __restrict__ v, float* __restrict__ o)
{
    const int fh = blockIdx.x, f = fh / NHEADS, h = fh % NHEADS;
    __shared__ float sk[16][SKPAD];
    __shared__ float sv[16][SKPAD];
    const int t = threadIdx.x;
    #pragma unroll
    for (int i = 0; i < 4; i++) {
        int id = t + i * 128, j = id >> 5, c4 = id & 31;
        size_t goff = ((size_t)(f * 16 + j)) * DIMM + h * HDIM + c4 * 4;
        *(float4*)(&sk[j][c4 * 4]) = *(const float4*)(k + goff);
        *(float4*)(&sv[j][c4 * 4]) = *(const float4*)(v + goff);
    }
    __syncthreads();
    const int warp = t >> 5, lane = t & 31;
    const float scale = 0.08838834764831844f;
    #pragma unroll
    for (int rr = 0; rr < 4; ++rr) {
        const int pos = blockIdx.y * 16 + warp * 4 + rr;
        if (pos >= HWTOK) break;
        const float4* q4 = (const float4*)(q + ((size_t)(f * HWTOK + pos)) * DIMM + h * HDIM);
        float logit = -1e30f;
        if (lane < 16) {
            float s = 0.f;
            #pragma unroll
            for (int c = 0; c < 32; c++) {
                float4 a = q4[c];
                float4 b = *(const float4*)(&sk[lane][c * 4]);
                s += a.x*b.x + a.y*b.y + a.z*b.z + a.w*b.w;
            }
            logit = s * scale;
        }
        float m = logit;
        #pragma unroll
        for (int off = 8; off > 0; off >>= 1) m = fmaxf(m, __shfl_xor_sync(0xffffffffu, m, off, 16));
        float e = (lane < 16) ? expf(logit - m) : 0.f;
        float ssum = e;
        #pragma unroll
        for (int off = 8; off > 0; off >>= 1) ssum += __shfl_xor_sync(0xffffffffu, ssum, off, 16);
        float att = (lane < 16) ? (e / ssum) : 0.f;
        float4 oacc = make_float4(0.f, 0.f, 0.f, 0.f);
        #pragma unroll
        for (int j = 0; j < 16; j++) {
            float aj = __shfl_sync(0xffffffffu, att, j);
            float4 vv = *(const float4*)(&sv[j][lane * 4]);
            oacc.x += aj*vv.x; oacc.y += aj*vv.y; oacc.z += aj*vv.z; oacc.w += aj*vv.w;
        }
        // Store tf32-rounded, K-permuted: old col 4L+j -> group (L>>1)*8, slot 2*j + (L&1)
        float* orow = o + ((size_t)(f * HWTOK + pos)) * DIMM + h * HDIM + (lane >> 1) * 8 + (lane & 1);
        orow[0] = __uint_as_float(f2tf32(oacc.x));
        orow[2] = __uint_as_float(f2tf32(oacc.y));
        orow[4] = __uint_as_float(f2tf32(oacc.z));
        orow[6] = __uint_as_float(f2tf32(oacc.w));
    }
}

// ---------------------------------------------------------------------------
// Launcher
// ---------------------------------------------------------------------------
extern "C" void kernel_launch(void* const* d_in, const int* in_sizes, int n_in,
                              void* d_out, int out_size)
{
    const float* x   = (const float*)d_in[0];
    const float* ctx = (const float*)d_in[1];
    const float* Wq  = (const float*)d_in[6];
    const float* bq  = (const float*)d_in[7];
    const float* Wk  = (const float*)d_in[8];
    const float* bk  = (const float*)d_in[9];
    const float* Wv  = (const float*)d_in[10];
    const float* bv  = (const float*)d_in[11];
    const float* Wo  = (const float*)d_in[12];
    const float* bo  = (const float*)d_in[13];
    const float* gq  = (const float*)d_in[14];
    const float* gk  = (const float*)d_in[15];
    float* out = (float*)d_out;

    float *xb, *wqb, *wob, *qb, *kb, *vb, *ob;
    cudaGetSymbolAddress((void**)&xb,  g_x);
    cudaGetSymbolAddress((void**)&wqb, g_wq);
    cudaGetSymbolAddress((void**)&wob, g_wo);
    cudaGetSymbolAddress((void**)&qb,  g_q);
    cudaGetSymbolAddress((void**)&kb,  g_k);
    cudaGetSymbolAddress((void**)&vb,  g_v);
    cudaGetSymbolAddress((void**)&ob,  g_o);

    cudaFuncSetAttribute(gemm_tc_kernel, cudaFuncAttributeMaxDynamicSharedMemorySize, GSMEM);
    const int lsmem = 2 * (BM * SROW + BN * SROW) * (int)sizeof(float);
    cudaFuncSetAttribute(gemm_tf32_kernel, cudaFuncAttributeMaxDynamicSharedMemorySize, lsmem);

    // Pre-round + K-permute inputs feeding the big GEMMs
    round_perm_kernel<<<2048, 256>>>(xb,  x,  (int)((size_t)L1TOK * DIMM / 8));
    round_perm_kernel<<<2048, 256>>>(wqb, Wq, (int)((size_t)DIMM  * DIMM / 8));
    round_perm_kernel<<<2048, 256>>>(wob, Wo, (int)((size_t)DIMM  * DIMM / 8));

    // Q projection: g_q = x @ Wq^T + bq
    {
        dim3 grid(DIMM / 128, (L1TOK + 255) / 256);
        gemm_tc_kernel<<<grid, 256, GSMEM>>>(xb, wqb, bq, qb, L1TOK);
    }
    // K / V projections (tiny)
    {
        dim3 grid(DIMM / BN, 1);
        gemm_tf32_kernel<<<grid, 256, lsmem>>>(ctx, Wk, bk, kb, LATOK, DIMM, KVD);
        gemm_tf32_kernel<<<grid, 256, lsmem>>>(ctx, Wv, bv, vb, LATOK, DIMM, KVD);
    }
    // RMSNorm
    rmsnorm_kernel<<<L1TOK, 256>>>(qb, gq);
    rmsnorm_kernel<<<LATOK, 256>>>(kb, gk);
    // Attention (writes tf32-rounded, K-permuted o)
    {
        dim3 grid(NFRAMES * NHEADS, (HWTOK + 15) / 16);
        attn_kernel<<<grid, 128>>>(qb, kb, vb, ob);
    }
    // Output projection: out = o @ Wo^T + bo
    {
        dim3 grid(DIMM / 128, (L1TOK + 255) / 256);
        gemm_tc_kernel<<<grid, 256, GSMEM>>>(ob, wob, bo, out, L1TOK);
    }
}